// round 17
// baseline (speedup 1.0000x reference)
#include <cuda_runtime.h>

#define BB  64
#define INN 512
#define HH  512
#define HID 16

// ---------------- packed f32x2 helpers (Blackwell sm_100+) ----------------
typedef unsigned long long u64;

static __device__ __forceinline__ u64 f2_fma(u64 a, u64 b, u64 c) {
    u64 r;
    asm("fma.rn.f32x2 %0, %1, %2, %3;" : "=l"(r) : "l"(a), "l"(b), "l"(c));
    return r;
}
static __device__ __forceinline__ u64 f2_add(u64 a, u64 b) {
    u64 r;
    asm("add.rn.f32x2 %0, %1, %2;" : "=l"(r) : "l"(a), "l"(b));
    return r;
}
static __device__ __forceinline__ u64 f2_pack(float x, float y) {
    u64 r;
    asm("mov.b64 %0, {%1, %2};" : "=l"(r) : "f"(x), "f"(y));
    return r;
}
static __device__ __forceinline__ float2 f2_unpack(u64 v) {
    float2 r;
    asm("mov.b64 {%0, %1}, %2;" : "=f"(r.x), "=f"(r.y) : "l"(v));
    return r;
}
// relu: pack/unpack are register aliasing (free); 2x FMNMX on the alu pipe.
static __device__ __forceinline__ u64 f2_relu(u64 v) {
    float2 t = f2_unpack(v);
    return f2_pack(fmaxf(t.x, 0.0f), fmaxf(t.y, 0.0f));
}

// One b-step: both j-lanes, 4 k's, accumulating into the given parity bank.
static __device__ __forceinline__ void body4(u64* accp, u64 q, u64 prb,
                                             const u64* u_bb, const u64* v_bb,
                                             const u64* d) {
#pragma unroll
    for (int kk = 0; kk < 4; ++kk) {
        u64 x = f2_fma(q, v_bb[kk], d[kk]);     // post*v + (w*t+b1)
        x = f2_fma(prb, u_bb[kk], x);           // + pre*u
        accp[kk] = f2_add(accp[kk], f2_relu(x));
    }
}

// ---------------- fused kernel, j-paired lanes ----------------
// out[i,j] = (1/B) * sum_b sum_k relu(pre[b,i]*u_k + post[b,j]*v_k + w_ij*t_k + b1_k) * W2_k + b2
//
// (Re-bench of round-16 kernel: previous run died to container infra --
//  same signature as rounds 1 and 8, both of which passed on re-bench.)
//
// R16 = R15 (43.0us) with the b-unroll widened 2 -> 4:
//  - 8 loads batch at iteration top (immediate offsets + pointer increment,
//    the addressing style R14 proved essential) -> ONE exposed L1 window per
//    4 b instead of per 2 b, and ~95 issues of math between stall points.
//  - loop overhead (branch + ptr IADDs) halves.
//  - acc[2][4]: parities 0/1 shared by (b,b+2)/(b+1,b+3) -- 8 chains, 2
//    far-apart adds per chain per iter.
//  - __launch_bounds__(128,7): occupancy is GRID-limited at 6.92 blocks/SM,
//    so the reg cap can relax to 73 (148*7=1036 >= 1024 blocks, still one
//    wave) -- room for the wider unroll without spills.
__global__ __launch_bounds__(128, 7)
void plasticity_fused(const float* __restrict__ pre,
                      const float* __restrict__ post,
                      const float* __restrict__ weight,
                      const float* __restrict__ W1,
                      const float* __restrict__ b1,
                      const float* __restrict__ W2,
                      const float* __restrict__ b2,
                      float* __restrict__ out) {
    const int tj = threadIdx.x & 63;       // 0..63
    const int ti = threadIdx.x >> 6;       // 0..1 (warp-uniform)
    const int i  = blockIdx.y * 2 + ti;
    const int j0 = blockIdx.x * 128 + tj * 2;

    // w_(i,j0), w_(i,j0+1) as a natural 64-bit pair (8B-aligned: j0 even).
    const u64 wpair = *reinterpret_cast<const u64*>(&weight[(size_t)i * HH + j0]);

    u64 grand = 0ull;    // sum_k W2_k * sum_b relu(...), lanes = (j0, j0+1)

#pragma unroll 1
    for (int chunk = 0; chunk < 4; ++chunk) {
        const int k0 = chunk * 4;
        // Per-chunk constants (hoisted out of the b-loop): 12 pairs = 24 regs.
        u64 u_bb[4], v_bb[4], d[4];
#pragma unroll
        for (int kk = 0; kk < 4; ++kk) {
            const int k = k0 + kk;
            const float uk = W1[k * 3 + 0];
            const float vk = W1[k * 3 + 1];
            const float tk = W1[k * 3 + 2];
            u_bb[kk] = f2_pack(uk, uk);
            v_bb[kk] = f2_pack(vk, vk);
            const u64 t_bb  = f2_pack(tk, tk);
            const u64 b1_bb = f2_pack(b1[k], b1[k]);
            d[kk] = f2_fma(wpair, t_bb, b1_bb);    // w_ij * t_k + b1_k (pair)
        }

        // 8 independent accumulator chains: [b-parity][kk].
        u64 acc[2][4] = { {0ull,0ull,0ull,0ull}, {0ull,0ull,0ull,0ull} };

        const float* pp = pre + i;                                  // +4*INN/iter
        const u64*   qq = reinterpret_cast<const u64*>(post + j0);  // +2*HH u64/iter

#pragma unroll 1
        for (int b = 0; b < BB; b += 4) {
            // Batch all 8 loads up front (one scoreboard window per 4 b).
            const float cp0 = pp[0];
            const float cp1 = pp[INN];
            const float cp2 = pp[2 * INN];
            const float cp3 = pp[3 * INN];
            const u64   q0  = qq[0];
            const u64   q1  = qq[HH / 2];
            const u64   q2  = qq[HH];
            const u64   q3  = qq[3 * (HH / 2)];
            pp += 4 * INN;
            qq += 2 * HH;

            body4(acc[0], q0, f2_pack(cp0, cp0), u_bb, v_bb, d);   // b
            body4(acc[1], q1, f2_pack(cp1, cp1), u_bb, v_bb, d);   // b+1
            body4(acc[0], q2, f2_pack(cp2, cp2), u_bb, v_bb, d);   // b+2
            body4(acc[1], q3, f2_pack(cp3, cp3), u_bb, v_bb, d);   // b+3
        }

        // Fold this chunk: grand += (acc_even + acc_odd) * W2_k.
#pragma unroll
        for (int kk = 0; kk < 4; ++kk) {
            const float w2k = W2[k0 + kk];
            grand = f2_fma(f2_add(acc[0][kk], acc[1][kk]),
                           f2_pack(w2k, w2k), grand);
        }
    }

    // Epilogue: scale by 1/B, add bias, store the j-pair as 64-bit.
    const float inv_b = 1.0f / (float)BB;
    const float bias2 = b2[0];
    u64 res = f2_fma(grand, f2_pack(inv_b, inv_b), f2_pack(bias2, bias2));
    *reinterpret_cast<u64*>(&out[(size_t)i * HH + j0]) = res;
}

// ---------------- launch ----------------
extern "C" void kernel_launch(void* const* d_in, const int* in_sizes, int n_in,
                              void* d_out, int out_size) {
    const float* pre    = (const float*)d_in[0];
    const float* post   = (const float*)d_in[1];
    const float* weight = (const float*)d_in[2];
    const float* W1     = (const float*)d_in[3];
    const float* b1     = (const float*)d_in[4];
    const float* W2     = (const float*)d_in[5];
    const float* b2     = (const float*)d_in[6];
    float* out = (float*)d_out;

    plasticity_fused<<<dim3(HH / 128, INN / 2), 128>>>(
        pre, post, weight, W1, b1, W2, b2, out);
}